// round 3
// baseline (speedup 1.0000x reference)
#include <cuda_runtime.h>
#include <math.h>

// Problem dims
#define BB   8
#define TT   2048
#define DD   300
#define KK   10
#define LL   8921
#define TP   2057     // TT + KK - 1
#define LP   8960     // L padded to 140*64
#define HTP  2064     // TP padded to multiple of 16
#define OP   304      // D padded for Wt rows

// Scratch (device globals; no allocation)
__device__ float g_Et[BB * DD * TT];     // embeddings transposed: [b][d][tau]
__device__ float g_Hs[BB * DD * HTP];    // conv output h: [b][d][t']
__device__ float g_Wt[KK * DD * OP];     // conv_w transposed: [k][i][o]
__device__ float g_Ut[DD * LP];          // U transposed: [d][l]

// ---------------------------------------------------------------------------
// Kernel 1: embedding gather + transpose  ->  Et[b][d][tau]
// ---------------------------------------------------------------------------
__global__ void k_gather(const int* __restrict__ ids, const float* __restrict__ emb) {
    __shared__ float sm[32][301];
    int b = blockIdx.y;
    int tau0 = blockIdx.x * 32;
    int tid = threadIdx.x;
    for (int idx = tid; idx < 32 * DD; idx += 256) {
        int r = idx / DD, c = idx - r * DD;
        int row = ids[b * TT + tau0 + r];
        sm[r][c] = emb[row * DD + c];
    }
    __syncthreads();
    for (int idx = tid; idx < DD * 32; idx += 256) {
        int i = idx >> 5, j = idx & 31;
        g_Et[(b * DD + i) * TT + tau0 + j] = sm[j][i];
    }
}

// ---------------------------------------------------------------------------
// Kernel 2: conv_w (O,I,K) -> Wt[k][i][o]
// ---------------------------------------------------------------------------
__global__ void k_wt(const float* __restrict__ w) {
    int idx = blockIdx.x * 256 + threadIdx.x;
    if (idx >= DD * DD * KK) return;
    int o = idx % DD;
    int rem = idx / DD;
    int i = rem % DD;
    int k = rem / DD;
    g_Wt[(k * DD + i) * OP + o] = w[(o * DD + i) * KK + k];
}

// ---------------------------------------------------------------------------
// Kernel 3: U (L,D) -> Ut[d][l]  (zero-padded to LP rows-of-l)
// ---------------------------------------------------------------------------
__global__ void k_ut(const float* __restrict__ U) {
    __shared__ float sm[32][33];
    int lt = blockIdx.x * 32, dt = blockIdx.y * 32;
    int tx = threadIdx.x, ty = threadIdx.y;
    int l = lt + ty, d = dt + tx;
    sm[ty][tx] = (l < LL && d < DD) ? U[l * DD + d] : 0.f;
    __syncthreads();
    int dd = dt + ty, ll = lt + tx;
    if (dd < DD) g_Ut[dd * LP + ll] = sm[tx][ty];
}

// ---------------------------------------------------------------------------
// Kernel 4: conv1d as GEMM over (k, i)  ->  Hs = relu(conv + bias)
//   block: 64 o-rows x 64 t'-cols, 256 threads, 4x4 microtile, BK=20
// ---------------------------------------------------------------------------
__global__ void __launch_bounds__(256) k_conv(const float* __restrict__ conv_b) {
    __shared__ float As[20][64];
    __shared__ float Bs[20][64];
    int t0 = blockIdx.x * 64;
    int o0 = blockIdx.y * 64;
    int b  = blockIdx.z;
    int tid = threadIdx.x;
    int tx = tid & 15, ty = tid >> 4;

    float acc[4][4] = {};
    const float* eb = g_Et + b * DD * TT;

    for (int k = 0; k < KK; k++) {
        const float* wk = g_Wt + k * DD * OP;
        int tshift = t0 + k - (KK - 1);
        for (int ic = 0; ic < 15; ic++) {
#pragma unroll
            for (int j = 0; j < 5; j++) {
                int idx = tid + j * 256;
                int c = idx >> 6, r = idx & 63;
                int o = o0 + r;
                As[c][r] = (o < DD) ? wk[(ic * 20 + c) * OP + o] : 0.f;
                int tau = tshift + r;
                Bs[c][r] = (tau >= 0 && tau < TT) ? eb[(ic * 20 + c) * TT + tau] : 0.f;
            }
            __syncthreads();
#pragma unroll
            for (int kk = 0; kk < 20; kk++) {
                float4 a4 = *(const float4*)&As[kk][ty * 4];
                float4 b4 = *(const float4*)&Bs[kk][tx * 4];
                float av[4] = {a4.x, a4.y, a4.z, a4.w};
                float bv[4] = {b4.x, b4.y, b4.z, b4.w};
#pragma unroll
                for (int m = 0; m < 4; m++)
#pragma unroll
                    for (int n = 0; n < 4; n++) acc[m][n] += av[m] * bv[n];
            }
            __syncthreads();
        }
    }

#pragma unroll
    for (int m = 0; m < 4; m++) {
        int o = o0 + ty * 4 + m;
        if (o >= DD) continue;
        float bias = conv_b[o];
#pragma unroll
        for (int n = 0; n < 4; n++) {
            int t = t0 + tx * 4 + n;
            if (t < TP) g_Hs[(b * DD + o) * HTP + t] = fmaxf(acc[m][n] + bias, 0.f);
        }
    }
}

// ---------------------------------------------------------------------------
// Kernel 5: fused score-GEMM + online softmax reduction
//   logits[b,l] = sum_t softmax_t(s[b,l,t]) * s[b,l,t] + fc_bias[l]
//   block: (b, 64 l-rows), loops over 33 t-tiles of 64
// ---------------------------------------------------------------------------
__global__ void __launch_bounds__(256) k_attn(const float* __restrict__ fc_bias,
                                              float* __restrict__ out) {
    __shared__ float As[20][64];
    __shared__ float Bs[20][64];
    int l0 = blockIdx.x * 64;
    int b  = blockIdx.y;
    int tid = threadIdx.x;
    int tx = tid & 15, ty = tid >> 4;

    const float* hb = g_Hs + b * DD * HTP;

    float m_run[4], se[4], ss[4];
#pragma unroll
    for (int m = 0; m < 4; m++) { m_run[m] = -INFINITY; se[m] = 0.f; ss[m] = 0.f; }

    for (int t0 = 0; t0 < TP; t0 += 64) {
        float acc[4][4] = {};
        for (int ic = 0; ic < 15; ic++) {
#pragma unroll
            for (int j = 0; j < 5; j++) {
                int idx = tid + j * 256;
                int c = idx >> 6, r = idx & 63;
                As[c][r] = g_Ut[(ic * 20 + c) * LP + l0 + r];   // padded rows are 0
                int t = t0 + r;
                Bs[c][r] = (t < TP) ? hb[(ic * 20 + c) * HTP + t] : 0.f;
            }
            __syncthreads();
#pragma unroll
            for (int kk = 0; kk < 20; kk++) {
                float4 a4 = *(const float4*)&As[kk][ty * 4];
                float4 b4 = *(const float4*)&Bs[kk][tx * 4];
                float av[4] = {a4.x, a4.y, a4.z, a4.w};
                float bv[4] = {b4.x, b4.y, b4.z, b4.w};
#pragma unroll
                for (int m = 0; m < 4; m++)
#pragma unroll
                    for (int n = 0; n < 4; n++) acc[m][n] += av[m] * bv[n];
            }
            __syncthreads();
        }

        // online softmax update per l-row (row spread across 16 tx lanes)
#pragma unroll
        for (int m = 0; m < 4; m++) {
            float mx = -INFINITY;
#pragma unroll
            for (int n = 0; n < 4; n++) {
                int t = t0 + tx * 4 + n;
                if (t < TP) mx = fmaxf(mx, acc[m][n]);
            }
#pragma unroll
            for (int off = 8; off; off >>= 1)
                mx = fmaxf(mx, __shfl_xor_sync(0xffffffffu, mx, off));

            float pe = 0.f, ps = 0.f;
#pragma unroll
            for (int n = 0; n < 4; n++) {
                int t = t0 + tx * 4 + n;
                if (t < TP) {
                    float p = __expf(acc[m][n] - mx);
                    pe += p;
                    ps += p * acc[m][n];
                }
            }
#pragma unroll
            for (int off = 8; off; off >>= 1) {
                pe += __shfl_xor_sync(0xffffffffu, pe, off);
                ps += __shfl_xor_sync(0xffffffffu, ps, off);
            }

            float mnew = fmaxf(m_run[m], mx);
            float ea = __expf(m_run[m] - mnew);
            float eb2 = __expf(mx - mnew);
            se[m] = se[m] * ea + pe * eb2;
            ss[m] = ss[m] * ea + ps * eb2;
            m_run[m] = mnew;
        }
    }

    if (tx == 0) {
#pragma unroll
        for (int m = 0; m < 4; m++) {
            int l = l0 + ty * 4 + m;
            if (l < LL) out[b * LL + l] = ss[m] / se[m] + fc_bias[l];
        }
    }
}

// ---------------------------------------------------------------------------
// Launch
// ---------------------------------------------------------------------------
extern "C" void kernel_launch(void* const* d_in, const int* in_sizes, int n_in,
                              void* d_out, int out_size) {
    // Identify inputs by element count (all distinct) for robustness.
    const int* ids = nullptr;
    const float *emb = nullptr, *cw = nullptr, *cb = nullptr, *U = nullptr, *fb = nullptr;
    for (int i = 0; i < n_in; i++) {
        switch (in_sizes[i]) {
            case BB * TT:          ids = (const int*)d_in[i];  break;
            case 50000 * DD:       emb = (const float*)d_in[i]; break;
            case DD * DD * KK:     cw  = (const float*)d_in[i]; break;
            case DD:               cb  = (const float*)d_in[i]; break;
            case LL * DD:          U   = (const float*)d_in[i]; break;
            case LL:               fb  = (const float*)d_in[i]; break;
            default: break;
        }
    }
    float* out = (float*)d_out;

    k_wt<<<(DD * DD * KK + 255) / 256, 256>>>(cw);
    k_ut<<<dim3(LP / 32, (DD + 31) / 32), dim3(32, 32)>>>(U);
    k_gather<<<dim3(TT / 32, BB), 256>>>(ids, emb);
    k_conv<<<dim3((TP + 63) / 64, (DD + 63) / 64, BB), 256>>>(cb);
    k_attn<<<dim3(LP / 64, BB), 256>>>(fb, out);
}

// round 4
// speedup vs baseline: 1.1017x; 1.1017x over previous
#include <cuda_runtime.h>
#include <math.h>

// Problem dims
#define BB   8
#define TT   2048
#define DD   300
#define KK   10
#define LL   8921
#define TP   2057     // TT + KK - 1
#define LP   8960     // L padded to 70*128
#define ETP  2208     // padded embed row: 9 halo + 2048 + headroom for t0+k+r
#define HTP2 2176     // padded conv-out row (17*128)
#define OP2  384      // o padded to 3*128

// Scratch (device globals, zero-initialized; padding regions never written)
__device__ float g_Et[BB * DD * ETP];     // padded embeddings: [b][d][9 + tau]
__device__ float g_Hs[BB * DD * HTP2];    // conv output h: [b][d][t']
__device__ float g_Wt[KK * DD * OP2];     // conv_w transposed: [k][i][o]
__device__ float g_Ut[DD * LP];           // U transposed: [d][l]

// ---------------------------------------------------------------------------
// Kernel 1: embedding gather + transpose -> Et[b][d][9 + tau]
// ---------------------------------------------------------------------------
__global__ void k_gather(const int* __restrict__ ids, const float* __restrict__ emb) {
    __shared__ float sm[32][301];
    int b = blockIdx.y;
    int tau0 = blockIdx.x * 32;
    int tid = threadIdx.x;
    for (int idx = tid; idx < 32 * DD; idx += 256) {
        int r = idx / DD, c = idx - r * DD;
        int row = ids[b * TT + tau0 + r];
        sm[r][c] = emb[row * DD + c];
    }
    __syncthreads();
    for (int idx = tid; idx < DD * 32; idx += 256) {
        int i = idx >> 5, j = idx & 31;
        g_Et[(b * DD + i) * ETP + 9 + tau0 + j] = sm[j][i];
    }
}

// ---------------------------------------------------------------------------
// Kernel 2: conv_w (O,I,K) -> Wt[k][i][o]  (o padded to OP2, pad stays 0)
// ---------------------------------------------------------------------------
__global__ void k_wt(const float* __restrict__ w) {
    int idx = blockIdx.x * 256 + threadIdx.x;
    if (idx >= DD * DD * KK) return;
    int o = idx % DD;
    int rem = idx / DD;
    int i = rem % DD;
    int k = rem / DD;
    g_Wt[(k * DD + i) * OP2 + o] = w[(o * DD + i) * KK + k];
}

// ---------------------------------------------------------------------------
// Kernel 3: U (L,D) -> Ut[d][l]  (zero-padded to LP)
// ---------------------------------------------------------------------------
__global__ void k_ut(const float* __restrict__ U) {
    __shared__ float sm[32][33];
    int lt = blockIdx.x * 32, dt = blockIdx.y * 32;
    int tx = threadIdx.x, ty = threadIdx.y;
    int l = lt + ty, d = dt + tx;
    sm[ty][tx] = (l < LL && d < DD) ? U[l * DD + d] : 0.f;
    __syncthreads();
    int dd = dt + ty, ll = lt + tx;
    if (dd < DD) g_Ut[dd * LP + ll] = sm[tx][ty];
}

// ---------------------------------------------------------------------------
// Shared 128x128 GEMM inner step: 8x8 microtile, 4 FMA per smem float
// ---------------------------------------------------------------------------
#define GEMM_MICRO(As, Bs, acc, tx, ty)                                       \
    _Pragma("unroll")                                                         \
    for (int kk = 0; kk < 20; kk++) {                                         \
        float4 a0 = *(const float4*)&As[kk][ty * 4];                          \
        float4 a1 = *(const float4*)&As[kk][64 + ty * 4];                     \
        float4 b0 = *(const float4*)&Bs[kk][tx * 4];                          \
        float4 b1 = *(const float4*)&Bs[kk][64 + tx * 4];                     \
        float av[8] = {a0.x, a0.y, a0.z, a0.w, a1.x, a1.y, a1.z, a1.w};       \
        float bv[8] = {b0.x, b0.y, b0.z, b0.w, b1.x, b1.y, b1.z, b1.w};       \
        _Pragma("unroll")                                                     \
        for (int m = 0; m < 8; m++)                                           \
            _Pragma("unroll")                                                 \
            for (int n = 0; n < 8; n++) acc[m][n] += av[m] * bv[n];           \
    }

// ---------------------------------------------------------------------------
// Kernel 4: conv1d as GEMM over (k,i) -> Hs = relu(conv + bias)
//   block: 128 o x 128 t', 256 threads, 8x8 microtile, BK=20, no inner branches
// ---------------------------------------------------------------------------
__global__ void __launch_bounds__(256, 2) k_conv(const float* __restrict__ conv_b) {
    __shared__ float As[20][128];
    __shared__ float Bs[20][128];
    int t0 = blockIdx.x * 128;
    int o0 = blockIdx.y * 128;
    int b  = blockIdx.z;
    int tid = threadIdx.x;
    int tx = tid & 15, ty = tid >> 4;

    float acc[8][8] = {};
    const float* eb = g_Et + b * DD * ETP;

    for (int k = 0; k < KK; k++) {
        const float* wk = g_Wt + k * DD * OP2 + o0;
        const float* ek = eb + t0 + k;          // Etp[i][t0+k+r] == E[t0+r+k-9]
        for (int ic = 0; ic < 15; ic++) {
#pragma unroll
            for (int j = 0; j < 10; j++) {
                int idx = tid + j * 256;
                int c = idx >> 7, r = idx & 127;
                As[c][r] = wk[(ic * 20 + c) * OP2 + r];
                Bs[c][r] = ek[(ic * 20 + c) * ETP + r];
            }
            __syncthreads();
            GEMM_MICRO(As, Bs, acc, tx, ty)
            __syncthreads();
        }
    }

#pragma unroll
    for (int m = 0; m < 8; m++) {
        int o = o0 + (m >> 2) * 64 + ty * 4 + (m & 3);
        if (o >= DD) continue;
        float bias = conv_b[o];
        float* hrow = g_Hs + (b * DD + o) * HTP2;
#pragma unroll
        for (int n = 0; n < 8; n++) {
            int t = t0 + (n >> 2) * 64 + tx * 4 + (n & 3);
            if (t < TP) hrow[t] = fmaxf(acc[m][n] + bias, 0.f);
        }
    }
}

// ---------------------------------------------------------------------------
// Kernel 5: fused score-GEMM + online softmax
//   logits[b,l] = sum_t softmax_t(s)*s + fc_bias, s = U.h
//   block: (b, 128 l-rows), 17 t-tiles of 128; state in smem
// ---------------------------------------------------------------------------
__global__ void __launch_bounds__(256, 2) k_attn(const float* __restrict__ fc_bias,
                                                 float* __restrict__ out) {
    __shared__ float As[20][128];
    __shared__ float Bs[20][128];
    __shared__ float s_m[128], s_e[128], s_s[128];
    int l0 = blockIdx.x * 128;
    int b  = blockIdx.y;
    int tid = threadIdx.x;
    int tx = tid & 15, ty = tid >> 4;

    if (tid < 128) { s_m[tid] = -INFINITY; s_e[tid] = 0.f; s_s[tid] = 0.f; }
    const float* hb = g_Hs + b * DD * HTP2;
    const float* ub = g_Ut + l0;
    __syncthreads();

    for (int t0 = 0; t0 < TP; t0 += 128) {
        float acc[8][8] = {};
        for (int ic = 0; ic < 15; ic++) {
#pragma unroll
            for (int j = 0; j < 10; j++) {
                int idx = tid + j * 256;
                int c = idx >> 7, r = idx & 127;
                As[c][r] = ub[(ic * 20 + c) * LP + r];           // pad rows are 0
                Bs[c][r] = hb[(ic * 20 + c) * HTP2 + t0 + r];    // tail is 0
            }
            __syncthreads();
            GEMM_MICRO(As, Bs, acc, tx, ty)
            __syncthreads();
        }

        // online softmax update, one l-row spread over the 16 tx lanes
#pragma unroll
        for (int m = 0; m < 8; m++) {
            int row = (m >> 2) * 64 + ty * 4 + (m & 3);
            float mx = -INFINITY;
#pragma unroll
            for (int n = 0; n < 8; n++) {
                int t = t0 + (n >> 2) * 64 + tx * 4 + (n & 3);
                if (t < TP) mx = fmaxf(mx, acc[m][n]);
            }
#pragma unroll
            for (int off = 8; off; off >>= 1)
                mx = fmaxf(mx, __shfl_xor_sync(0xffffffffu, mx, off));

            float pe = 0.f, ps = 0.f;
#pragma unroll
            for (int n = 0; n < 8; n++) {
                int t = t0 + (n >> 2) * 64 + tx * 4 + (n & 3);
                if (t < TP) {
                    float p = __expf(acc[m][n] - mx);
                    pe += p;
                    ps += p * acc[m][n];
                }
            }
#pragma unroll
            for (int off = 8; off; off >>= 1) {
                pe += __shfl_xor_sync(0xffffffffu, pe, off);
                ps += __shfl_xor_sync(0xffffffffu, ps, off);
            }

            float mo = s_m[row];
            float mn = fmaxf(mo, mx);
            float ea = __expf(mo - mn);
            float eb2 = __expf(mx - mn);
            if (tx == 0) {
                s_e[row] = s_e[row] * ea + pe * eb2;
                s_s[row] = s_s[row] * ea + ps * eb2;
                s_m[row] = mn;
            }
        }
        __syncthreads();
    }

    if (tid < 128) {
        int l = l0 + tid;
        if (l < LL) out[b * LL + l] = s_s[tid] / s_e[tid] + fc_bias[l];
    }
}

// ---------------------------------------------------------------------------
// Launch
// ---------------------------------------------------------------------------
extern "C" void kernel_launch(void* const* d_in, const int* in_sizes, int n_in,
                              void* d_out, int out_size) {
    const int* ids = nullptr;
    const float *emb = nullptr, *cw = nullptr, *cb = nullptr, *U = nullptr, *fb = nullptr;
    for (int i = 0; i < n_in; i++) {
        switch (in_sizes[i]) {
            case BB * TT:          ids = (const int*)d_in[i];  break;
            case 50000 * DD:       emb = (const float*)d_in[i]; break;
            case DD * DD * KK:     cw  = (const float*)d_in[i]; break;
            case DD:               cb  = (const float*)d_in[i]; break;
            case LL * DD:          U   = (const float*)d_in[i]; break;
            case LL:               fb  = (const float*)d_in[i]; break;
            default: break;
        }
    }
    float* out = (float*)d_out;

    k_wt<<<(DD * DD * KK + 255) / 256, 256>>>(cw);
    k_ut<<<dim3(LP / 32, (DD + 31) / 32), dim3(32, 32)>>>(U);
    k_gather<<<dim3(TT / 32, BB), 256>>>(ids, emb);
    k_conv<<<dim3((TP + 127) / 128, (OP2) / 128, BB), 256>>>(cb);
    k_attn<<<dim3(LP / 128, BB), 256>>>(fb, out);
}